// round 3
// baseline (speedup 1.0000x reference)
#include <cuda_runtime.h>

#define NN 10000
#define NE 640000
#define CH 128

// ---------------- device scratch (no allocation allowed) ----------------
__device__ __align__(16) float g_dinv[NN];         // deg(w), then rsqrt(deg)
__device__ int   g_row[NE];
__device__ int   g_col[NE];
__device__ int   g_cnt[NN];                        // in-degree counts
__device__ int   g_off[NN + 1];                    // CSR offsets (by col)
__device__ int   g_cursor[NN];                     // fill cursors
__device__ int   g_csr_src[NE];                    // source node per CSR slot
__device__ float g_csr_w[NE];                      // norm per CSR slot
__device__ __align__(16) float g_bufA[NN * CH];
__device__ __align__(16) float g_bufB[NN * CH];
__device__ __align__(16) float g_bufC[NN * CH];
__device__ __align__(16) float g_vk[3 * CH];       // vk[k*128 + i]
__device__ float g_c0;

// ---------------- stage 1: degree + histogram ----------------
__global__ void k_init() {
    int n = blockIdx.x * blockDim.x + threadIdx.x;
    if (n < NN) { g_dinv[n] = 1.0f; g_cnt[n] = 0; }   // self-loop weight = 1
}

__global__ void k_edge_deg(const int* __restrict__ ei,
                           const float* __restrict__ ew) {
    int e = blockIdx.x * blockDim.x + threadIdx.x;
    if (e >= NE) return;
    int r = ei[e];          // edge_index delivered as int32 by the harness
    int c = ei[NE + e];
    g_row[e] = r;
    g_col[e] = c;
    atomicAdd(&g_dinv[c], ew[e]);
    atomicAdd(&g_cnt[c], 1);
}

__global__ void k_dinv() {
    int n = blockIdx.x * blockDim.x + threadIdx.x;
    if (n < NN) g_dinv[n] = rsqrtf(g_dinv[n]);   // deg >= 1 (self loop)
}

// ---------------- stage 2: exclusive scan (single block) ----------------
__global__ void k_scan() {
    __shared__ int sh[1024];
    __shared__ int carry;
    int t = threadIdx.x;
    if (t == 0) carry = 0;
    __syncthreads();
    for (int base = 0; base < NN; base += 1024) {
        int i = base + t;
        int v = (i < NN) ? g_cnt[i] : 0;
        sh[t] = v;
        __syncthreads();
#pragma unroll
        for (int off = 1; off < 1024; off <<= 1) {
            int add = (t >= off) ? sh[t - off] : 0;
            __syncthreads();
            sh[t] += add;
            __syncthreads();
        }
        int excl = sh[t] - v + carry;   // carry not yet updated this tile
        if (i < NN) { g_off[i] = excl; g_cursor[i] = excl; }
        __syncthreads();
        if (t == 1023) carry += sh[1023];
        __syncthreads();
    }
    if (t == 0) g_off[NN] = NE;
}

// ---------------- stage 3: CSR fill + norm ----------------
__global__ void k_fill(const float* __restrict__ ew) {
    int e = blockIdx.x * blockDim.x + threadIdx.x;
    if (e >= NE) return;
    int r = g_row[e];
    int c = g_col[e];
    float w = g_dinv[r] * ew[e] * g_dinv[c];
    int pos = atomicAdd(&g_cursor[c], 1);
    g_csr_src[pos] = r;
    g_csr_w[pos] = w;
}

// ---------------- GEMM body: C[m,n] = sum_k A'[m,k] * W[n,k] -------------
// A' = relu(A + bias) when RELU_BIAS. 256 thr -> 64 rows x 128 cols.
template <bool RELU_BIAS>
__device__ __forceinline__ void gemm_body(const float* __restrict__ A,
                                          const float* __restrict__ W,
                                          const float* __restrict__ bias,
                                          float* __restrict__ Cout, int M) {
    __shared__ __align__(16) float As[64][32];
    __shared__ float Ws[128][33];

    int t = threadIdx.x;
    int lane = t & 31;
    int warp = t >> 5;
    int row0 = blockIdx.x * 64;

    float acc[8][4];
#pragma unroll
    for (int i = 0; i < 8; i++)
#pragma unroll
        for (int j = 0; j < 4; j++) acc[i][j] = 0.f;

    for (int k0 = 0; k0 < 128; k0 += 32) {
#pragma unroll
        for (int it = 0; it < 2; it++) {
            int idx = t + it * 256;
            int r = idx >> 3;
            int c4 = idx & 7;
            int gr = row0 + r;
            float4 v = make_float4(0.f, 0.f, 0.f, 0.f);
            if (gr < M) {
                v = *(const float4*)&A[(size_t)gr * CH + k0 + c4 * 4];
                if (RELU_BIAS) {
                    int kb = k0 + c4 * 4;
                    v.x = fmaxf(v.x + bias[kb + 0], 0.f);
                    v.y = fmaxf(v.y + bias[kb + 1], 0.f);
                    v.z = fmaxf(v.z + bias[kb + 2], 0.f);
                    v.w = fmaxf(v.w + bias[kb + 3], 0.f);
                }
            }
            *(float4*)&As[r][c4 * 4] = v;
        }
#pragma unroll
        for (int it = 0; it < 4; it++) {
            int idx = t + it * 256;
            int n = idx >> 3;
            int c4 = idx & 7;
            float4 v = *(const float4*)&W[(size_t)n * CH + k0 + c4 * 4];
            Ws[n][c4 * 4 + 0] = v.x;
            Ws[n][c4 * 4 + 1] = v.y;
            Ws[n][c4 * 4 + 2] = v.z;
            Ws[n][c4 * 4 + 3] = v.w;
        }
        __syncthreads();

#pragma unroll
        for (int kk = 0; kk < 32; kk++) {
            float wv[4];
#pragma unroll
            for (int j = 0; j < 4; j++) wv[j] = Ws[lane + 32 * j][kk];
#pragma unroll
            for (int i = 0; i < 8; i++) {
                float a = As[warp * 8 + i][kk];
#pragma unroll
                for (int j = 0; j < 4; j++) acc[i][j] = fmaf(a, wv[j], acc[i][j]);
            }
        }
        __syncthreads();
    }

#pragma unroll
    for (int i = 0; i < 8; i++) {
        int gr = row0 + warp * 8 + i;
        if (gr < M) {
#pragma unroll
            for (int j = 0; j < 4; j++)
                Cout[(size_t)gr * CH + lane + 32 * j] = acc[i][j];
        }
    }
}

__global__ void k_gemm_l1(const float* __restrict__ x,
                          const float* __restrict__ W1) {
    gemm_body<false>(x, W1, x /*unused*/, g_bufA, NN);
}

__global__ void k_gemm_l2(const float* __restrict__ W2,
                          const float* __restrict__ b1) {
    gemm_body<true>(g_bufB, W2, b1, g_bufA, NN);
}

// ---------------- stage 4: CSR gather (atomic-free aggregation) ----------
// one warp per node: dst[n] = dinv[n]^2 * src[n] + sum_e w_e * src[src_e]
__device__ __forceinline__ void gather_body(const float* __restrict__ src,
                                            float* __restrict__ dst) {
    int gt = blockIdx.x * blockDim.x + threadIdx.x;
    int n = gt >> 5;
    int lane = gt & 31;
    if (n >= NN) return;

    const float4* s4 = (const float4*)src;
    float di = g_dinv[n];
    float sc = di * di;
    float4 own = s4[n * 32 + lane];
    float4 acc = make_float4(own.x * sc, own.y * sc, own.z * sc, own.w * sc);

    int beg = g_off[n];
    int end = g_off[n + 1];
    int j = beg;
    for (; j + 4 <= end; j += 4) {
        int r0 = g_csr_src[j + 0], r1 = g_csr_src[j + 1];
        int r2 = g_csr_src[j + 2], r3 = g_csr_src[j + 3];
        float w0 = g_csr_w[j + 0], w1 = g_csr_w[j + 1];
        float w2 = g_csr_w[j + 2], w3 = g_csr_w[j + 3];
        float4 v0 = s4[r0 * 32 + lane];
        float4 v1 = s4[r1 * 32 + lane];
        float4 v2 = s4[r2 * 32 + lane];
        float4 v3 = s4[r3 * 32 + lane];
        acc.x = fmaf(w0, v0.x, fmaf(w1, v1.x, fmaf(w2, v2.x, fmaf(w3, v3.x, acc.x))));
        acc.y = fmaf(w0, v0.y, fmaf(w1, v1.y, fmaf(w2, v2.y, fmaf(w3, v3.y, acc.y))));
        acc.z = fmaf(w0, v0.z, fmaf(w1, v1.z, fmaf(w2, v2.z, fmaf(w3, v3.z, acc.z))));
        acc.w = fmaf(w0, v0.w, fmaf(w1, v1.w, fmaf(w2, v2.w, fmaf(w3, v3.w, acc.w))));
    }
    for (; j < end; j++) {
        int r = g_csr_src[j];
        float w = g_csr_w[j];
        float4 v = s4[r * 32 + lane];
        acc.x = fmaf(w, v.x, acc.x);
        acc.y = fmaf(w, v.y, acc.y);
        acc.z = fmaf(w, v.z, acc.z);
        acc.w = fmaf(w, v.w, acc.w);
    }
    ((float4*)dst)[n * 32 + lane] = acc;
}

__global__ void k_gather1() { gather_body(g_bufA, g_bufB); }
__global__ void k_gather2() { gather_body(g_bufA, g_bufC); }

// ---------------- collapse conv1d + fc into vk / c0 ----------------
__global__ void k_prep_vk(const float* __restrict__ cw,   // [128][128][3]
                          const float* __restrict__ cb,   // [128]
                          const float* __restrict__ fw,   // [1][128]
                          const float* __restrict__ fb) { // [1]
    int t = blockIdx.x * blockDim.x + threadIdx.x;
    if (t < 3 * CH) {
        int k = t >> 7;
        int i = t & 127;
        float s = 0.f;
        for (int h = 0; h < CH; h++) s += fw[h] * cw[h * (CH * 3) + i * 3 + k];
        g_vk[k * CH + i] = s;
    }
    if (t == 3 * CH) {
        float s = fb[0];
        for (int h = 0; h < CH; h++) s += fw[h] * cb[h];
        g_c0 = s;
    }
}

// -------- final: out[n] = c0 + sum_k sum_i vk[i,k]*relu(agg+b2)[n+k-1,i] ---
__global__ void k_final(const float* __restrict__ b2,
                        float* __restrict__ out) {
    int gt = blockIdx.x * blockDim.x + threadIdx.x;
    int n = gt >> 5;
    int lane = gt & 31;
    if (n >= NN) return;
    const float4* agg4 = (const float4*)g_bufC;
    float4 bb = ((const float4*)b2)[lane];
    float acc = 0.f;
#pragma unroll
    for (int k = 0; k < 3; k++) {
        int m = n + k - 1;
        if (m < 0 || m >= NN) continue;   // SAME zero padding
        float4 hv = agg4[m * 32 + lane];
        float4 vv = ((const float4*)g_vk)[k * 32 + lane];
        acc += fmaxf(hv.x + bb.x, 0.f) * vv.x
             + fmaxf(hv.y + bb.y, 0.f) * vv.y
             + fmaxf(hv.z + bb.z, 0.f) * vv.z
             + fmaxf(hv.w + bb.w, 0.f) * vv.w;
    }
#pragma unroll
    for (int o = 16; o; o >>= 1) acc += __shfl_xor_sync(0xffffffffu, acc, o);
    if (lane == 0) out[n] = g_c0 + acc;
}

// ---------------- launch ----------------
extern "C" void kernel_launch(void* const* d_in, const int* in_sizes, int n_in,
                              void* d_out, int out_size) {
    (void)in_sizes; (void)n_in; (void)out_size;
    const float* x  = (const float*)d_in[0];
    const int*   ei = (const int*)d_in[1];     // int64 in reference -> int32 here
    const float* ew = (const float*)d_in[2];
    const float* W1 = (const float*)d_in[3];
    const float* b1 = (const float*)d_in[4];
    const float* W2 = (const float*)d_in[5];
    const float* b2 = (const float*)d_in[6];
    const float* cw = (const float*)d_in[7];
    const float* cb = (const float*)d_in[8];
    const float* fw = (const float*)d_in[9];
    const float* fb = (const float*)d_in[10];
    float* out = (float*)d_out;

    const int TB = 256;

    // CSR build + normalization
    k_init<<<(NN + TB - 1) / TB, TB>>>();
    k_edge_deg<<<(NE + TB - 1) / TB, TB>>>(ei, ew);
    k_dinv<<<(NN + TB - 1) / TB, TB>>>();
    k_scan<<<1, 1024>>>();
    k_fill<<<(NE + TB - 1) / TB, TB>>>(ew);

    // layer 1: bufA = x @ W1^T ; bufB = A_hat * bufA
    k_gemm_l1<<<(NN + 63) / 64, TB>>>(x, W1);
    k_gather1<<<(NN * 32 + TB - 1) / TB, TB>>>();

    // layer 2: bufA = relu(bufB + b1) @ W2^T ; bufC = A_hat * bufA
    k_gemm_l2<<<(NN + 63) / 64, TB>>>(W2, b1);
    k_gather2<<<(NN * 32 + TB - 1) / TB, TB>>>();

    // conv1d + fc collapsed
    k_prep_vk<<<1, 512>>>(cw, cb, fw, fb);
    k_final<<<(NN * 32 + TB - 1) / TB, TB>>>(b2, out);
}